// round 1
// baseline (speedup 1.0000x reference)
#include <cuda_runtime.h>
#include <cuda_bf16.h>
#include <math.h>

#define N_NODES 50000
#define N_EDGES 600000
#define DIM 128
#define NUM_CLASSES 10
#define EPSF 1e-15f
#define MAX_NORM (1.0f - 1e-5f)

#define BM 16                      // nodes per tile in transform kernel
#define TPITCH 20                  // padded row pitch (floats) for t2[k][r]
#define WPITCH 129                 // padded pitch for transposed W in smem

// smem layout (floats): Wsh[128*129] | t2[128*20] | red[64] | fac[16]
#define SM_W    0
#define SM_T2   (DIM * WPITCH)
#define SM_RED  (SM_T2 + DIM * TPITCH)
#define SM_FAC  (SM_RED + 64)
#define SMEM_FLOATS (SM_FAC + 16)
#define SMEM_BYTES (SMEM_FLOATS * 4)

// scratch (device globals: no allocation allowed)
__device__ float g_y[N_NODES * DIM];
__device__ float g_agg[N_NODES * DIM];
__device__ int   g_mult;   // 1 if edge_index is int32, 2 if int64 (stride in int32 words)

// ---------------------------------------------------------------------------
// dtype detection: int64 edge values < 50000 have zero high words at odd int32
// slots; random int32 indices make 64 consecutive odd slots all-zero impossible.
__global__ void detect_kernel(const int* __restrict__ e32) {
    __shared__ int bad;
    if (threadIdx.x == 0) bad = 0;
    __syncthreads();
    if (e32[2 * threadIdx.x + 1] != 0) atomicOr(&bad, 1);
    __syncthreads();
    if (threadIdx.x == 0) g_mult = bad ? 1 : 2;
}

// ---------------------------------------------------------------------------
__global__ void fill_kernel(float4* __restrict__ p, int n4) {
    int i = blockIdx.x * blockDim.x + threadIdx.x;
    int stride = gridDim.x * blockDim.x;
    float4 z = make_float4(0.f, 0.f, 0.f, 0.f);
    for (; i < n4; i += stride) p[i] = z;
}

// ---------------------------------------------------------------------------
// Fused: (optional relu) -> logmap0 -> h = t @ W^T + b -> expmap0
// Block: 128 threads, BM=16 nodes per tile, persistent over tiles.
__global__ void __launch_bounds__(128, 2)
transform_kernel(const float* __restrict__ in, const float* __restrict__ W,
                 const float* __restrict__ bias, float* __restrict__ out,
                 int do_relu) {
    extern __shared__ float sm[];
    float* Wsh = sm + SM_W;
    float* t2  = sm + SM_T2;
    float* red = sm + SM_RED;
    float* fac = sm + SM_FAC;

    const int tid  = threadIdx.x;
    const int lane = tid & 31;
    const int wid  = tid >> 5;

    // Load W transposed into smem: Wsh[k*129 + j] = W[j*128 + k]
    for (int idx = tid; idx < DIM * DIM; idx += 128) {
        int j = idx >> 7, k = idx & 127;
        Wsh[k * WPITCH + j] = W[idx];
    }
    const float bj = bias[tid];
    __syncthreads();

    const int ntiles = N_NODES / BM;   // 3125, exact
    for (int tile = blockIdx.x; tile < ntiles; tile += gridDim.x) {
        const int node0 = tile * BM;

        // ---- load inputs (thread tid owns column tid of all BM rows) ----
        float xv[BM];
#pragma unroll
        for (int r = 0; r < BM; r++) {
            float v = in[(node0 + r) * DIM + tid];
            if (do_relu) v = fmaxf(v, 0.f);
            xv[r] = v;
        }

        // ---- per-row sum of squares, reduced across 128 threads ----
        float ss[BM];
#pragma unroll
        for (int r = 0; r < BM; r++) {
            float s = xv[r] * xv[r];
            s += __shfl_xor_sync(0xffffffff, s, 16);
            s += __shfl_xor_sync(0xffffffff, s, 8);
            s += __shfl_xor_sync(0xffffffff, s, 4);
            s += __shfl_xor_sync(0xffffffff, s, 2);
            s += __shfl_xor_sync(0xffffffff, s, 1);
            ss[r] = s;
        }
        if (lane == 0) {
#pragma unroll
            for (int r = 0; r < BM; r++) red[wid * BM + r] = ss[r];
        }
        __syncthreads();
        if (tid < BM) {
            float s = red[0 * BM + tid] + red[1 * BM + tid] +
                      red[2 * BM + tid] + red[3 * BM + tid];
            float n = fmaxf(sqrtf(s), EPSF);
            fac[tid] = atanhf(fminf(n, MAX_NORM)) / n;   // logmap0 factor
        }
        __syncthreads();

        // ---- write t transposed: t2[k=tid][r], float4-packed ----
#pragma unroll
        for (int q = 0; q < 4; q++) {
            float4 tv;
            tv.x = xv[4 * q + 0] * fac[4 * q + 0];
            tv.y = xv[4 * q + 1] * fac[4 * q + 1];
            tv.z = xv[4 * q + 2] * fac[4 * q + 2];
            tv.w = xv[4 * q + 3] * fac[4 * q + 3];
            *(float4*)&t2[tid * TPITCH + 4 * q] = tv;
        }
        __syncthreads();

        // ---- GEMM inner loop: thread tid computes output column tid for BM nodes
        float acc[BM];
#pragma unroll
        for (int r = 0; r < BM; r++) acc[r] = 0.f;

#pragma unroll 4
        for (int k = 0; k < DIM; k++) {
            float w = Wsh[k * WPITCH + tid];
            float4 a = *(const float4*)&t2[k * TPITCH + 0];
            float4 b = *(const float4*)&t2[k * TPITCH + 4];
            float4 c = *(const float4*)&t2[k * TPITCH + 8];
            float4 d = *(const float4*)&t2[k * TPITCH + 12];
            acc[0]  = fmaf(w, a.x, acc[0]);
            acc[1]  = fmaf(w, a.y, acc[1]);
            acc[2]  = fmaf(w, a.z, acc[2]);
            acc[3]  = fmaf(w, a.w, acc[3]);
            acc[4]  = fmaf(w, b.x, acc[4]);
            acc[5]  = fmaf(w, b.y, acc[5]);
            acc[6]  = fmaf(w, b.z, acc[6]);
            acc[7]  = fmaf(w, b.w, acc[7]);
            acc[8]  = fmaf(w, c.x, acc[8]);
            acc[9]  = fmaf(w, c.y, acc[9]);
            acc[10] = fmaf(w, c.z, acc[10]);
            acc[11] = fmaf(w, c.w, acc[11]);
            acc[12] = fmaf(w, d.x, acc[12]);
            acc[13] = fmaf(w, d.y, acc[13]);
            acc[14] = fmaf(w, d.z, acc[14]);
            acc[15] = fmaf(w, d.w, acc[15]);
        }

        // ---- epilogue: + bias, expmap0 ----
        float hv[BM];
#pragma unroll
        for (int r = 0; r < BM; r++) hv[r] = acc[r] + bj;

#pragma unroll
        for (int r = 0; r < BM; r++) {
            float s = hv[r] * hv[r];
            s += __shfl_xor_sync(0xffffffff, s, 16);
            s += __shfl_xor_sync(0xffffffff, s, 8);
            s += __shfl_xor_sync(0xffffffff, s, 4);
            s += __shfl_xor_sync(0xffffffff, s, 2);
            s += __shfl_xor_sync(0xffffffff, s, 1);
            ss[r] = s;
        }
        __syncthreads();   // protect red[] against stragglers of prior phase
        if (lane == 0) {
#pragma unroll
            for (int r = 0; r < BM; r++) red[wid * BM + r] = ss[r];
        }
        __syncthreads();
        if (tid < BM) {
            float s = red[0 * BM + tid] + red[1 * BM + tid] +
                      red[2 * BM + tid] + red[3 * BM + tid];
            float n = fmaxf(sqrtf(s), EPSF);
            fac[tid] = tanhf(n) / n;                     // expmap0 factor
        }
        __syncthreads();

#pragma unroll
        for (int r = 0; r < BM; r++)
            out[(node0 + r) * DIM + tid] = fac[r] * hv[r];
        __syncthreads();   // fac/red reused next tile
    }
}

// ---------------------------------------------------------------------------
// Scatter-add: one warp per edge; 16B no-return vector atomics.
__device__ __forceinline__ void red_add_v4(float* p, float4 v) {
    asm volatile("red.global.add.v4.f32 [%0], {%1, %2, %3, %4};"
                 :: "l"(p), "f"(v.x), "f"(v.y), "f"(v.z), "f"(v.w)
                 : "memory");
}

__global__ void scatter_kernel(const int* __restrict__ e32,
                               const float* __restrict__ y,
                               float* __restrict__ agg) {
    const long long gid = (long long)blockIdx.x * blockDim.x + threadIdx.x;
    const int e = (int)(gid >> 5);
    if (e >= N_EDGES) return;
    const int lane = (int)(gid & 31);
    const int mult = g_mult;
    const int src = e32[(long long)e * mult];
    const int dst = e32[(long long)(N_EDGES + e) * mult];
    float4 v = __ldg((const float4*)&y[src * DIM + lane * 4]);
    red_add_v4(&agg[dst * DIM + lane * 4], v);
}

// ---------------------------------------------------------------------------
// Classifier: relu -> logmap0 -> t @ Wc^T + bc. One warp per node.
__global__ void classifier_kernel(const float* __restrict__ agg,
                                  const float* __restrict__ Wc,
                                  const float* __restrict__ bc,
                                  float* __restrict__ out) {
    __shared__ float Wcs[NUM_CLASSES * DIM];
    __shared__ float bcs[NUM_CLASSES];
    const int tid = threadIdx.x;
    for (int i = tid; i < NUM_CLASSES * DIM; i += blockDim.x) Wcs[i] = Wc[i];
    if (tid < NUM_CLASSES) bcs[tid] = bc[tid];
    __syncthreads();

    const int lane = tid & 31;
    const int wid  = tid >> 5;
    const int node = blockIdx.x * (blockDim.x >> 5) + wid;
    if (node >= N_NODES) return;

    float4 h = *(const float4*)&agg[node * DIM + lane * 4];
    h.x = fmaxf(h.x, 0.f); h.y = fmaxf(h.y, 0.f);
    h.z = fmaxf(h.z, 0.f); h.w = fmaxf(h.w, 0.f);

    float s = h.x * h.x + h.y * h.y + h.z * h.z + h.w * h.w;
    s += __shfl_xor_sync(0xffffffff, s, 16);
    s += __shfl_xor_sync(0xffffffff, s, 8);
    s += __shfl_xor_sync(0xffffffff, s, 4);
    s += __shfl_xor_sync(0xffffffff, s, 2);
    s += __shfl_xor_sync(0xffffffff, s, 1);
    float n = fmaxf(sqrtf(s), EPSF);
    float f = atanhf(fminf(n, MAX_NORM)) / n;
    float4 t = make_float4(f * h.x, f * h.y, f * h.z, f * h.w);

#pragma unroll
    for (int c = 0; c < NUM_CLASSES; c++) {
        float4 w = *(const float4*)&Wcs[c * DIM + lane * 4];
        float p = t.x * w.x + t.y * w.y + t.z * w.z + t.w * w.w;
        p += __shfl_xor_sync(0xffffffff, p, 16);
        p += __shfl_xor_sync(0xffffffff, p, 8);
        p += __shfl_xor_sync(0xffffffff, p, 4);
        p += __shfl_xor_sync(0xffffffff, p, 2);
        p += __shfl_xor_sync(0xffffffff, p, 1);
        if (lane == 0) out[node * NUM_CLASSES + c] = p + bcs[c];
    }
}

// ---------------------------------------------------------------------------
extern "C" void kernel_launch(void* const* d_in, const int* in_sizes, int n_in,
                              void* d_out, int out_size) {
    const int*   e32 = (const int*)d_in[0];
    const float* x   = (const float*)d_in[1];
    const float* W1  = (const float*)d_in[2];
    const float* b1  = (const float*)d_in[3];
    const float* W2  = (const float*)d_in[4];
    const float* b2  = (const float*)d_in[5];
    const float* Wc  = (const float*)d_in[6];
    const float* bc  = (const float*)d_in[7];
    float* out = (float*)d_out;

    float* y;
    float* agg;
    cudaGetSymbolAddress((void**)&y,   g_y);
    cudaGetSymbolAddress((void**)&agg, g_agg);

    cudaFuncSetAttribute(transform_kernel,
                         cudaFuncAttributeMaxDynamicSharedMemorySize, SMEM_BYTES);

    const int n4 = N_NODES * DIM / 4;
    const int scatter_blocks = (N_EDGES * 32 + 255) / 256;

    detect_kernel<<<1, 64>>>(e32);
    fill_kernel<<<800, 256>>>((float4*)agg, n4);
    transform_kernel<<<296, 128, SMEM_BYTES>>>(x, W1, b1, y, 0);
    scatter_kernel<<<scatter_blocks, 256>>>(e32, y, agg);
    transform_kernel<<<296, 128, SMEM_BYTES>>>(agg, W2, b2, y, 1);
    fill_kernel<<<800, 256>>>((float4*)agg, n4);
    scatter_kernel<<<scatter_blocks, 256>>>(e32, y, agg);
    classifier_kernel<<<(N_NODES + 7) / 8, 256>>>(agg, Wc, bc, out);
}

// round 3
// speedup vs baseline: 1.2790x; 1.2790x over previous
#include <cuda_runtime.h>
#include <cuda_bf16.h>
#include <math.h>

#define N_NODES 50000
#define N_EDGES 600000
#define DIM 128
#define NUM_CLASSES 10
#define EPSF 1e-15f
#define MAX_NORM (1.0f - 1e-5f)

#define BM 16                      // nodes per tile in transform kernel
#define TPITCH 20                  // padded row pitch (floats) for t2[k][r]; 80B (16B-aligned)
#define WPITCH 129                 // padded pitch for transposed W in smem

// smem layout (floats): Wsh[128*129] | t2[128*20] | red[64] | fac[16]
#define SM_W    0
#define SM_T2   (DIM * WPITCH)
#define SM_RED  (SM_T2 + DIM * TPITCH)
#define SM_FAC  (SM_RED + 64)
#define SMEM_FLOATS (SM_FAC + 16)
#define SMEM_BYTES (SMEM_FLOATS * 4)

#define SCAN_B 1024
#define SCAN_NB ((N_NODES + SCAN_B - 1) / SCAN_B)   // 49

typedef unsigned long long u64;

// scratch (device globals: no allocation allowed)
__device__ float g_y[N_NODES * DIM];
__device__ float g_agg[N_NODES * DIM];
__device__ int   g_mult;                 // 1 if edge_index int32, 2 if int64 (stride in i32 words)
__device__ int   g_count[N_NODES];       // histogram
__device__ int   g_cursor[N_NODES];      // bucket cursors
__device__ int   g_rowstart[N_NODES + 1];
__device__ int   g_bsum[SCAN_NB];
__device__ int   g_boff[SCAN_NB];
__device__ int   g_esrc[N_EDGES];        // CSR: src node per slot, grouped by dst

// ---------------------------------------------------------------------------
// packed fp32x2 helpers (Blackwell dual-rate FFMA2 — PTX-only)
__device__ __forceinline__ u64 fma2(u64 a, u64 b, u64 c) {
    u64 d;
    asm("fma.rn.f32x2 %0, %1, %2, %3;" : "=l"(d) : "l"(a), "l"(b), "l"(c));
    return d;
}
__device__ __forceinline__ u64 pack2(float lo, float hi) {
    u64 r;
    asm("mov.b64 %0, {%1, %2};" : "=l"(r) : "f"(lo), "f"(hi));
    return r;
}
__device__ __forceinline__ void unpack2(u64 v, float& lo, float& hi) {
    asm("mov.b64 {%0, %1}, %2;" : "=f"(lo), "=f"(hi) : "l"(v));
}

// ---------------------------------------------------------------------------
// dtype detection: int64 edge values < 50000 have zero high words at odd int32
// slots; random int32 indices make 64 consecutive odd slots all-zero impossible.
__global__ void detect_kernel(const int* __restrict__ e32) {
    __shared__ int bad;
    if (threadIdx.x == 0) bad = 0;
    __syncthreads();
    if (e32[2 * threadIdx.x + 1] != 0) atomicOr(&bad, 1);
    __syncthreads();
    if (threadIdx.x == 0) g_mult = bad ? 1 : 2;
}

// ---------------------------------------------------------------------------
__global__ void zero_int_kernel(int* __restrict__ p, int n) {
    int i = blockIdx.x * blockDim.x + threadIdx.x;
    int stride = gridDim.x * blockDim.x;
    for (; i < n; i += stride) p[i] = 0;
}

__global__ void hist_kernel(const int* __restrict__ e32, int* __restrict__ cnt) {
    int e = blockIdx.x * blockDim.x + threadIdx.x;
    if (e >= N_EDGES) return;
    int m = g_mult;
    int dst = e32[(long long)(N_EDGES + e) * m];
    atomicAdd(&cnt[dst], 1);
}

// exclusive scan phase 1: per-block scan of 1024 elements
__global__ void scan1_kernel(const int* __restrict__ cnt, int* __restrict__ rs,
                             int* __restrict__ bsum) {
    __shared__ int wsum[32];
    const int b = blockIdx.x, t = threadIdx.x;
    const int i = b * SCAN_B + t;
    const int lane = t & 31, w = t >> 5;
    int v = (i < N_NODES) ? cnt[i] : 0;
    int x = v;
#pragma unroll
    for (int d = 1; d < 32; d <<= 1) {
        int y = __shfl_up_sync(0xffffffffu, x, d);
        if (lane >= d) x += y;
    }
    if (lane == 31) wsum[w] = x;
    __syncthreads();
    if (w == 0) {
        int s = wsum[lane];
#pragma unroll
        for (int d = 1; d < 32; d <<= 1) {
            int y = __shfl_up_sync(0xffffffffu, s, d);
            if (lane >= d) s += y;
        }
        wsum[lane] = s;
    }
    __syncthreads();
    int excl = x - v + (w ? wsum[w - 1] : 0);
    if (i < N_NODES) rs[i] = excl;
    if (t == SCAN_B - 1) bsum[b] = excl + v;
}

// phase 2: scan the 49 block totals (single block, 64 threads)
__global__ void scan2_kernel(const int* __restrict__ bsum, int* __restrict__ boff) {
    __shared__ int w0tot;
    const int t = threadIdx.x;
    const int lane = t & 31, w = t >> 5;
    int v = (t < SCAN_NB) ? bsum[t] : 0;
    int x = v;
#pragma unroll
    for (int d = 1; d < 32; d <<= 1) {
        int y = __shfl_up_sync(0xffffffffu, x, d);
        if (lane >= d) x += y;
    }
    if (w == 0 && lane == 31) w0tot = x;
    __syncthreads();
    int excl = x - v + (w ? w0tot : 0);
    if (t < SCAN_NB) boff[t] = excl;
}

// phase 3: add block offsets, init cursors, cap rowstart
__global__ void scan3_kernel(int* __restrict__ rs, const int* __restrict__ boff,
                             int* __restrict__ cursor) {
    int i = blockIdx.x * SCAN_B + threadIdx.x;
    if (i < N_NODES) {
        int v = rs[i] + boff[blockIdx.x];
        rs[i] = v;
        cursor[i] = v;
    }
    if (i == 0) rs[N_NODES] = N_EDGES;
}

// bucket scatter: place src ids grouped by dst
__global__ void build_kernel(const int* __restrict__ e32, int* __restrict__ cursor,
                             int* __restrict__ esrc) {
    int e = blockIdx.x * blockDim.x + threadIdx.x;
    if (e >= N_EDGES) return;
    int m = g_mult;
    int src = e32[(long long)e * m];
    int dst = e32[(long long)(N_EDGES + e) * m];
    int pos = atomicAdd(&cursor[dst], 1);
    esrc[pos] = src;
}

// ---------------------------------------------------------------------------
// Aggregation: one warp per dst node, register accumulation, no atomics.
__global__ void __launch_bounds__(256)
gather_kernel(const int* __restrict__ esrc, const int* __restrict__ rs,
              const float* __restrict__ y, float* __restrict__ agg) {
    const int lane = threadIdx.x & 31;
    const int wid  = threadIdx.x >> 5;
    const int node = blockIdx.x * (blockDim.x >> 5) + wid;
    if (node >= N_NODES) return;

    const int s = rs[node];
    const int e = rs[node + 1];

    float4 a0 = make_float4(0.f, 0.f, 0.f, 0.f);
    float4 a1 = make_float4(0.f, 0.f, 0.f, 0.f);
    int i = s;
    for (; i + 1 < e; i += 2) {
        int s0 = __ldg(&esrc[i]);
        int s1 = __ldg(&esrc[i + 1]);
        float4 v0 = __ldg((const float4*)&y[(long long)s0 * DIM + lane * 4]);
        float4 v1 = __ldg((const float4*)&y[(long long)s1 * DIM + lane * 4]);
        a0.x += v0.x; a0.y += v0.y; a0.z += v0.z; a0.w += v0.w;
        a1.x += v1.x; a1.y += v1.y; a1.z += v1.z; a1.w += v1.w;
    }
    if (i < e) {
        int s0 = __ldg(&esrc[i]);
        float4 v0 = __ldg((const float4*)&y[(long long)s0 * DIM + lane * 4]);
        a0.x += v0.x; a0.y += v0.y; a0.z += v0.z; a0.w += v0.w;
    }
    float4 r;
    r.x = a0.x + a1.x; r.y = a0.y + a1.y; r.z = a0.z + a1.z; r.w = a0.w + a1.w;
    *(float4*)&agg[(long long)node * DIM + lane * 4] = r;
}

// ---------------------------------------------------------------------------
// Fused: (optional relu) -> logmap0 -> h = t @ W^T + b -> expmap0
// 128 threads, BM=16 nodes/tile, persistent; packed f32x2 FMA inner loop.
__global__ void __launch_bounds__(128, 2)
transform_kernel(const float* __restrict__ in, const float* __restrict__ W,
                 const float* __restrict__ bias, float* __restrict__ out,
                 int do_relu) {
    extern __shared__ float sm[];
    float* Wsh = sm + SM_W;
    float* t2  = sm + SM_T2;
    float* red = sm + SM_RED;
    float* fac = sm + SM_FAC;

    const int tid  = threadIdx.x;
    const int lane = tid & 31;
    const int wid  = tid >> 5;

    // Load W transposed into smem: Wsh[k*129 + j] = W[j*128 + k]
    for (int idx = tid; idx < DIM * DIM; idx += 128) {
        int j = idx >> 7, k = idx & 127;
        Wsh[k * WPITCH + j] = W[idx];
    }
    const float bj = bias[tid];
    __syncthreads();

    const int ntiles = N_NODES / BM;   // 3125, exact
    for (int tile = blockIdx.x; tile < ntiles; tile += gridDim.x) {
        const int node0 = tile * BM;

        // ---- load inputs (thread tid owns column tid of all BM rows) ----
        float xv[BM];
#pragma unroll
        for (int r = 0; r < BM; r++) {
            float v = in[(node0 + r) * DIM + tid];
            if (do_relu) v = fmaxf(v, 0.f);
            xv[r] = v;
        }

        // ---- per-row sum of squares, reduced across 128 threads ----
        float ss[BM];
#pragma unroll
        for (int r = 0; r < BM; r++) {
            float s = xv[r] * xv[r];
            s += __shfl_xor_sync(0xffffffff, s, 16);
            s += __shfl_xor_sync(0xffffffff, s, 8);
            s += __shfl_xor_sync(0xffffffff, s, 4);
            s += __shfl_xor_sync(0xffffffff, s, 2);
            s += __shfl_xor_sync(0xffffffff, s, 1);
            ss[r] = s;
        }
        if (lane == 0) {
#pragma unroll
            for (int r = 0; r < BM; r++) red[wid * BM + r] = ss[r];
        }
        __syncthreads();
        if (tid < BM) {
            float s = red[0 * BM + tid] + red[1 * BM + tid] +
                      red[2 * BM + tid] + red[3 * BM + tid];
            float n = fmaxf(sqrtf(s), EPSF);
            fac[tid] = atanhf(fminf(n, MAX_NORM)) / n;   // logmap0 factor
        }
        __syncthreads();

        // ---- write t transposed: t2[k=tid][r], float4-packed ----
#pragma unroll
        for (int q = 0; q < 4; q++) {
            float4 tv;
            tv.x = xv[4 * q + 0] * fac[4 * q + 0];
            tv.y = xv[4 * q + 1] * fac[4 * q + 1];
            tv.z = xv[4 * q + 2] * fac[4 * q + 2];
            tv.w = xv[4 * q + 3] * fac[4 * q + 3];
            *(float4*)&t2[tid * TPITCH + 4 * q] = tv;
        }
        __syncthreads();

        // ---- GEMM inner loop (packed f32x2): thread tid = output column tid
        u64 acc2[8];
#pragma unroll
        for (int j = 0; j < 8; j++) acc2[j] = 0ULL;

#pragma unroll 4
        for (int k = 0; k < DIM; k++) {
            float w = Wsh[k * WPITCH + tid];
            u64 ww = pack2(w, w);
            const float* trow = &t2[k * TPITCH];
            ulonglong2 p0 = *(const ulonglong2*)(trow + 0);
            ulonglong2 p1 = *(const ulonglong2*)(trow + 4);
            ulonglong2 p2 = *(const ulonglong2*)(trow + 8);
            ulonglong2 p3 = *(const ulonglong2*)(trow + 12);
            acc2[0] = fma2(ww, p0.x, acc2[0]);
            acc2[1] = fma2(ww, p0.y, acc2[1]);
            acc2[2] = fma2(ww, p1.x, acc2[2]);
            acc2[3] = fma2(ww, p1.y, acc2[3]);
            acc2[4] = fma2(ww, p2.x, acc2[4]);
            acc2[5] = fma2(ww, p2.y, acc2[5]);
            acc2[6] = fma2(ww, p3.x, acc2[6]);
            acc2[7] = fma2(ww, p3.y, acc2[7]);
        }

        // ---- epilogue: + bias, expmap0 ----
        float hv[BM];
#pragma unroll
        for (int j = 0; j < 8; j++) {
            float lo, hi;
            unpack2(acc2[j], lo, hi);
            hv[2 * j + 0] = lo + bj;
            hv[2 * j + 1] = hi + bj;
        }

#pragma unroll
        for (int r = 0; r < BM; r++) {
            float s = hv[r] * hv[r];
            s += __shfl_xor_sync(0xffffffff, s, 16);
            s += __shfl_xor_sync(0xffffffff, s, 8);
            s += __shfl_xor_sync(0xffffffff, s, 4);
            s += __shfl_xor_sync(0xffffffff, s, 2);
            s += __shfl_xor_sync(0xffffffff, s, 1);
            ss[r] = s;
        }
        __syncthreads();   // protect red[] against stragglers of prior phase
        if (lane == 0) {
#pragma unroll
            for (int r = 0; r < BM; r++) red[wid * BM + r] = ss[r];
        }
        __syncthreads();
        if (tid < BM) {
            float s = red[0 * BM + tid] + red[1 * BM + tid] +
                      red[2 * BM + tid] + red[3 * BM + tid];
            float n = fmaxf(sqrtf(s), EPSF);
            fac[tid] = tanhf(n) / n;                     // expmap0 factor
        }
        __syncthreads();

#pragma unroll
        for (int r = 0; r < BM; r++)
            out[(node0 + r) * DIM + tid] = fac[r] * hv[r];
        __syncthreads();   // fac/red reused next tile
    }
}

// ---------------------------------------------------------------------------
// Classifier: relu -> logmap0 -> t @ Wc^T + bc. One warp per node.
__global__ void classifier_kernel(const float* __restrict__ agg,
                                  const float* __restrict__ Wc,
                                  const float* __restrict__ bc,
                                  float* __restrict__ out) {
    __shared__ float Wcs[NUM_CLASSES * DIM];
    __shared__ float bcs[NUM_CLASSES];
    const int tid = threadIdx.x;
    for (int i = tid; i < NUM_CLASSES * DIM; i += blockDim.x) Wcs[i] = Wc[i];
    if (tid < NUM_CLASSES) bcs[tid] = bc[tid];
    __syncthreads();

    const int lane = tid & 31;
    const int wid  = tid >> 5;
    const int node = blockIdx.x * (blockDim.x >> 5) + wid;
    if (node >= N_NODES) return;

    float4 h = *(const float4*)&agg[node * DIM + lane * 4];
    h.x = fmaxf(h.x, 0.f); h.y = fmaxf(h.y, 0.f);
    h.z = fmaxf(h.z, 0.f); h.w = fmaxf(h.w, 0.f);

    float s = h.x * h.x + h.y * h.y + h.z * h.z + h.w * h.w;
    s += __shfl_xor_sync(0xffffffff, s, 16);
    s += __shfl_xor_sync(0xffffffff, s, 8);
    s += __shfl_xor_sync(0xffffffff, s, 4);
    s += __shfl_xor_sync(0xffffffff, s, 2);
    s += __shfl_xor_sync(0xffffffff, s, 1);
    float n = fmaxf(sqrtf(s), EPSF);
    float f = atanhf(fminf(n, MAX_NORM)) / n;
    float4 t = make_float4(f * h.x, f * h.y, f * h.z, f * h.w);

#pragma unroll
    for (int c = 0; c < NUM_CLASSES; c++) {
        float4 w = *(const float4*)&Wcs[c * DIM + lane * 4];
        float p = t.x * w.x + t.y * w.y + t.z * w.z + t.w * w.w;
        p += __shfl_xor_sync(0xffffffff, p, 16);
        p += __shfl_xor_sync(0xffffffff, p, 8);
        p += __shfl_xor_sync(0xffffffff, p, 4);
        p += __shfl_xor_sync(0xffffffff, p, 2);
        p += __shfl_xor_sync(0xffffffff, p, 1);
        if (lane == 0) out[node * NUM_CLASSES + c] = p + bcs[c];
    }
}

// ---------------------------------------------------------------------------
extern "C" void kernel_launch(void* const* d_in, const int* in_sizes, int n_in,
                              void* d_out, int out_size) {
    const int*   e32 = (const int*)d_in[0];
    const float* x   = (const float*)d_in[1];
    const float* W1  = (const float*)d_in[2];
    const float* b1  = (const float*)d_in[3];
    const float* W2  = (const float*)d_in[4];
    const float* b2  = (const float*)d_in[5];
    const float* Wc  = (const float*)d_in[6];
    const float* bc  = (const float*)d_in[7];
    float* out = (float*)d_out;

    float *y, *agg;
    int *cnt, *cur, *rs, *bs, *bo, *es;
    cudaGetSymbolAddress((void**)&y,   g_y);
    cudaGetSymbolAddress((void**)&agg, g_agg);
    cudaGetSymbolAddress((void**)&cnt, g_count);
    cudaGetSymbolAddress((void**)&cur, g_cursor);
    cudaGetSymbolAddress((void**)&rs,  g_rowstart);
    cudaGetSymbolAddress((void**)&bs,  g_bsum);
    cudaGetSymbolAddress((void**)&bo,  g_boff);
    cudaGetSymbolAddress((void**)&es,  g_esrc);

    cudaFuncSetAttribute(transform_kernel,
                         cudaFuncAttributeMaxDynamicSharedMemorySize, SMEM_BYTES);

    const int eblocks = (N_EDGES + 255) / 256;
    const int gblocks = (N_NODES + 7) / 8;     // 8 warps/block

    // CSR build (once; edges identical for both layers)
    detect_kernel<<<1, 64>>>(e32);
    zero_int_kernel<<<196, 256>>>(cnt, N_NODES);
    hist_kernel<<<eblocks, 256>>>(e32, cnt);
    scan1_kernel<<<SCAN_NB, SCAN_B>>>(cnt, rs, bs);
    scan2_kernel<<<1, 64>>>(bs, bo);
    scan3_kernel<<<SCAN_NB, SCAN_B>>>(rs, bo, cur);
    build_kernel<<<eblocks, 256>>>(e32, cur, es);

    // layer 1
    transform_kernel<<<296, 128, SMEM_BYTES>>>(x, W1, b1, y, 0);
    gather_kernel<<<gblocks, 256>>>(es, rs, y, agg);
    // layer 2
    transform_kernel<<<296, 128, SMEM_BYTES>>>(agg, W2, b2, y, 1);
    gather_kernel<<<gblocks, 256>>>(es, rs, y, agg);
    // classifier
    classifier_kernel<<<gblocks, 256>>>(agg, Wc, bc, out);
}